// round 4
// baseline (speedup 1.0000x reference)
#include <cuda_runtime.h>
#include <math_constants.h>

#define NN 262144
#define EE (NN * 32)
#define VEC 4   // edges per thread in edge kernel

// Packed per-node data: 2 x float4 per node (32B, single L2 sector), 8 MB, L2-resident
//   nodeA = { actualArea, c2 = aA^2/(area*rho), fA = area*rho, p }
//   nodeB = { vx, vy, ax, ay }
__device__ float4 g_node[NN * 2];
// SPLIT accumulator arrays so each edge's two reds land on different L2 slices.
//   accA = { kSum1x, kSum1y, accelx, accely }
//   accB = { kSum2, source, kernelSum, pad }
// Zero at module load; final_kernel re-zeroes after reading (self-cleaning).
__device__ float4 g_accA[NN];
__device__ float4 g_accB[NN];

__global__ void prep_kernel(const float* __restrict__ area,
                            const float* __restrict__ actualArea,
                            const float* __restrict__ rho,
                            const float* __restrict__ density,
                            const float* __restrict__ pressure2,
                            const float2* __restrict__ vel,
                            const float2* __restrict__ acc)
{
    int n = blockIdx.x * blockDim.x + threadIdx.x;
    if (n >= NN) return;
    float aA = actualArea[n];
    float ar = area[n];
    float r  = rho[n];
    float fA = ar * r;
    float c2 = (aA * aA) / fA;
    float dr = density[n] * r;
    float p  = pressure2[n] / (dr * dr);
    float2 v = vel[n];
    float2 a = acc[n];
    g_node[2 * n + 0] = make_float4(aA, c2, fA, p);
    g_node[2 * n + 1] = make_float4(v.x, v.y, a.x, a.y);
}

__device__ __forceinline__ void red_add_v4(float4* addr, float a, float b, float c, float d) {
    asm volatile("red.global.add.v4.f32 [%0], {%1, %2, %3, %4};"
                 :: "l"(addr), "f"(a), "f"(b), "f"(c), "f"(d) : "memory");
}

__global__ void edge_kernel(const int* __restrict__ nbr,       // [2, E]
                            const float* __restrict__ radial,  // [E]
                            const float2* __restrict__ dirs,   // [E, 2]
                            const float* __restrict__ support_p,
                            const float* __restrict__ dt_p)
{
    int t = blockIdx.x * blockDim.x + threadIdx.x;
    if (t >= EE / VEC) return;

    float h  = __ldg(support_p);
    float dt = __ldg(dt_p);
    const float C_W = 7.0f / CUDART_PI_F;
    float K = (C_W / (h * h * h)) * 20.0f;

    // Vectorized, streaming (evict-first) loads of the edge arrays
    int4   ii  = __ldcs(((const int4*)nbr) + t);
    int4   jj  = __ldcs(((const int4*)(nbr + EE)) + t);
    float4 qq  = __ldcs(((const float4*)radial) + t);
    float4 d01 = __ldcs(((const float4*)dirs) + 2 * t);
    float4 d23 = __ldcs(((const float4*)dirs) + 2 * t + 1);

    int idx_i[VEC] = { ii.x, ii.y, ii.z, ii.w };
    int idx_j[VEC] = { jj.x, jj.y, jj.z, jj.w };
    float  q[VEC]  = { qq.x, qq.y, qq.z, qq.w };
    float2 d[VEC]  = { make_float2(d01.x, d01.y), make_float2(d01.z, d01.w),
                       make_float2(d23.x, d23.y), make_float2(d23.z, d23.w) };

    // Batch all gathers first: MLP = 16 in-flight LDG.128 hides L2 latency
    float4 ja[VEC], jb[VEC], ia[VEC], ib[VEC];
#pragma unroll
    for (int k = 0; k < VEC; k++) {
        ja[k] = g_node[2 * idx_j[k] + 0];
        jb[k] = g_node[2 * idx_j[k] + 1];
        ia[k] = g_node[2 * idx_i[k] + 0];
        ib[k] = g_node[2 * idx_i[k] + 1];
    }

#pragma unroll
    for (int k = 0; k < VEC; k++) {
        float om = 1.0f - q[k];
        float mag = K * q[k] * om * om * om;
        float gx = -d[k].x * mag;
        float gy = -d[k].y * mag;
        float grad2 = gx * gx + gy * gy;

        // kSum1
        float kx = ja[k].x * gx;
        float ky = ja[k].x * gy;
        // kSum2
        float k2 = ja[k].y * grad2;
        // pressure accel: facA = -(area*rho)[j]
        float pc = -ja[k].z * (ia[k].w + ja[k].w);
        float ax = pc * gx;
        float ay = pc * gy;
        // source: -dt * aA[j] * dot(vi - vj, g)
        float src = -dt * ja[k].x *
                    ((ib[k].x - jb[k].x) * gx + (ib[k].y - jb[k].y) * gy);
        // kernelSum: dt^2 * aA[j] * dot(ai - aj, g)
        float ks = dt * dt * ja[k].x *
                   ((ib[k].z - jb[k].z) * gx + (ib[k].w - jb[k].w) * gy);

        red_add_v4(&g_accA[idx_i[k]], kx, ky, ax, ay);
        red_add_v4(&g_accB[idx_i[k]], k2, src, ks, 0.0f);
    }
}

__global__ void final_kernel(float* __restrict__ out, const float* __restrict__ dt_p)
{
    int n = blockIdx.x * blockDim.x + threadIdx.x;
    if (n >= NN) return;
    float dt = __ldg(dt_p);
    float4 A  = g_accA[n];         // {kSum1x, kSum1y, accelx, accely}
    float4 B  = g_accB[n];         // {kSum2, source, kernelSum, pad}
    float4 na = g_node[2 * n + 0]; // {aA, c2, fA, p}
    float fac = -dt * dt * na.x;
    float mass = na.z;             // area * rho
    float alpha = (fac / mass) * (A.x * A.x + A.y * A.y) + fac * B.x;
    out[5 * n + 0] = alpha;
    out[5 * n + 1] = A.z;
    out[5 * n + 2] = A.w;
    out[5 * n + 3] = B.y;
    out[5 * n + 4] = B.z;
    // Self-zero the accumulators for the next graph replay (deterministic:
    // globals start zeroed at module load, and every execution leaves zeros).
    g_accA[n] = make_float4(0.f, 0.f, 0.f, 0.f);
    g_accB[n] = make_float4(0.f, 0.f, 0.f, 0.f);
}

extern "C" void kernel_launch(void* const* d_in, const int* in_sizes, int n_in,
                              void* d_out, int out_size)
{
    const float*  fluidArea         = (const float*)d_in[0];
    const float*  fluidActualArea   = (const float*)d_in[1];
    const float*  fluidRestDensity  = (const float*)d_in[2];
    const float*  fluidDensity      = (const float*)d_in[3];
    const float*  fluidPressure2    = (const float*)d_in[4];
    const float2* fluidPredVel      = (const float2*)d_in[5];
    const float2* fluidPredAccel    = (const float2*)d_in[6];
    const float*  fluidRadial       = (const float*)d_in[7];
    const float2* fluidDistances    = (const float2*)d_in[8];
    const int*    fluidNeighbors    = (const int*)d_in[9];
    const float*  support           = (const float*)d_in[10];
    const float*  dt                = (const float*)d_in[11];
    float* out = (float*)d_out;

    prep_kernel<<<(NN + 255) / 256, 256>>>(fluidArea, fluidActualArea,
                                           fluidRestDensity, fluidDensity,
                                           fluidPressure2, fluidPredVel,
                                           fluidPredAccel);
    int nthreads = EE / VEC;
    edge_kernel<<<(nthreads + 127) / 128, 128>>>(fluidNeighbors, fluidRadial,
                                                 fluidDistances, support, dt);
    final_kernel<<<(NN + 255) / 256, 256>>>(out, dt);
}